// round 6
// baseline (speedup 1.0000x reference)
#include <cuda_runtime.h>
#include <cuda_bf16.h>
#include <cstdint>
#include <cstddef>

// Problem constants
#define BB    4
#define NN    4096
#define DIN   256
#define DOUT  128
#define COS_EPS    0.001f
#define THRESHOLD  0.1f
#define LEAKY      0.01f
#define FIX_WIN    2e-4f
#define MAXFIX     (1u << 22)

// ---------------------------------------------------------------------------
// Scratch (static device globals; no allocations allowed)
// ---------------------------------------------------------------------------
__device__ float          g_h[BB * NN * DOUT];
__device__ __nv_bfloat16  g_hi[BB * NN * DOUT];
__device__ __nv_bfloat16  g_lo[BB * NN * DOUT];
__device__ float          g_norm[BB * NN];
__device__ float          g_rnorm[BB * NN];
__device__ unsigned int   g_fix_cnt;
__device__ unsigned int   g_fix[MAXFIX];

__device__ __forceinline__ uint32_t smem_u32(const void* p) {
    uint32_t a;
    asm("{ .reg .u64 t; cvta.to.shared.u64 t, %1; cvt.u32.u64 %0, t; }"
        : "=r"(a) : "l"(p));
    return a;
}

__device__ __forceinline__ void ldsm_x4(uint32_t* r, uint32_t addr) {
    asm volatile("ldmatrix.sync.aligned.m8n8.x4.shared.b16 {%0,%1,%2,%3}, [%4];"
                 : "=r"(r[0]), "=r"(r[1]), "=r"(r[2]), "=r"(r[3]) : "r"(addr));
}
__device__ __forceinline__ void mma_bf16(float* d, const uint32_t* a, const uint32_t* b) {
    asm volatile(
        "mma.sync.aligned.m16n8k16.row.col.f32.bf16.bf16.f32 "
        "{%0,%1,%2,%3}, {%4,%5,%6,%7}, {%8,%9}, {%0,%1,%2,%3};"
        : "+f"(d[0]), "+f"(d[1]), "+f"(d[2]), "+f"(d[3])
        : "r"(a[0]), "r"(a[1]), "r"(a[2]), "r"(a[3]), "r"(b[0]), "r"(b[1]));
}

extern __shared__ char smem_raw[];

// ---------------------------------------------------------------------------
// Kernel A: h = leaky_relu(z @ W), fp32 SIMT
// ---------------------------------------------------------------------------
#define Z_ROWLEN 132
__global__ void __launch_bounds__(256, 1)
gemm1_kernel(const float* __restrict__ z, const float* __restrict__ W)
{
    float* smem = (float*)smem_raw;
    float* Zs = smem;
    float* Ws = smem + 64 * Z_ROWLEN;

    const int m0  = blockIdx.x * 128;
    const int tid = threadIdx.x;
    const int tm  = tid >> 4;
    const int tn  = tid & 15;

    float acc[8][8];
#pragma unroll
    for (int i = 0; i < 8; i++)
#pragma unroll
        for (int j = 0; j < 8; j++) acc[i][j] = 0.f;

    for (int k0 = 0; k0 < DIN; k0 += 64) {
#pragma unroll
        for (int t = 0; t < 8; t++) {
            int idx = tid + t * 256;
            int r   = idx >> 4;
            int kk  = (idx & 15) << 2;
            float4 v = *(const float4*)(z + (size_t)(m0 + r) * DIN + k0 + kk);
            Zs[(kk + 0) * Z_ROWLEN + r] = v.x;
            Zs[(kk + 1) * Z_ROWLEN + r] = v.y;
            Zs[(kk + 2) * Z_ROWLEN + r] = v.z;
            Zs[(kk + 3) * Z_ROWLEN + r] = v.w;
        }
#pragma unroll
        for (int t = 0; t < 8; t++) {
            int idx = tid + t * 256;
            int kk  = idx >> 5;
            int n4  = (idx & 31) << 2;
            float4 v = *(const float4*)(W + (size_t)(k0 + kk) * DOUT + n4);
            *(float4*)&Ws[kk * DOUT + n4] = v;
        }
        __syncthreads();

#pragma unroll 8
        for (int k = 0; k < 64; k++) {
            float a[8], b[8];
            *(float4*)(a)     = *(float4*)&Zs[k * Z_ROWLEN + tm * 8];
            *(float4*)(a + 4) = *(float4*)&Zs[k * Z_ROWLEN + tm * 8 + 4];
            *(float4*)(b)     = *(float4*)&Ws[k * DOUT + tn * 8];
            *(float4*)(b + 4) = *(float4*)&Ws[k * DOUT + tn * 8 + 4];
#pragma unroll
            for (int i = 0; i < 8; i++)
#pragma unroll
                for (int j = 0; j < 8; j++)
                    acc[i][j] += a[i] * b[j];
        }
        __syncthreads();
    }

#pragma unroll
    for (int i = 0; i < 8; i++) {
        int row = m0 + tm * 8 + i;
        float v[8];
#pragma unroll
        for (int j = 0; j < 8; j++) {
            float x = acc[i][j];
            v[j] = (x > 0.f) ? x : LEAKY * x;
        }
        float* dst = g_h + (size_t)row * DOUT + tn * 8;
        *(float4*)(dst)     = make_float4(v[0], v[1], v[2], v[3]);
        *(float4*)(dst + 4) = make_float4(v[4], v[5], v[6], v[7]);
    }
}

// ---------------------------------------------------------------------------
// Kernel B: per row — norm, rnorm, bf16 hi/lo split. One warp per row.
// ---------------------------------------------------------------------------
__global__ void __launch_bounds__(256)
split_kernel()
{
    int row  = blockIdx.x * 8 + (threadIdx.x >> 5);
    int lane = threadIdx.x & 31;
    const float* hr = g_h + (size_t)row * DOUT;

    float4 x = ((const float4*)hr)[lane];
    float s = x.x * x.x + x.y * x.y + x.z * x.z + x.w * x.w;
#pragma unroll
    for (int off = 16; off > 0; off >>= 1)
        s += __shfl_xor_sync(0xFFFFFFFFu, s, off);

    __nv_bfloat16 h0 = __float2bfloat16(x.x);
    __nv_bfloat16 h1 = __float2bfloat16(x.y);
    __nv_bfloat16 h2 = __float2bfloat16(x.z);
    __nv_bfloat16 h3 = __float2bfloat16(x.w);
    __nv_bfloat16 l0 = __float2bfloat16(x.x - __bfloat162float(h0));
    __nv_bfloat16 l1 = __float2bfloat16(x.y - __bfloat162float(h1));
    __nv_bfloat16 l2 = __float2bfloat16(x.z - __bfloat162float(h2));
    __nv_bfloat16 l3 = __float2bfloat16(x.w - __bfloat162float(h3));

    __nv_bfloat162 hp0 = __nv_bfloat162(h0, h1), hp1 = __nv_bfloat162(h2, h3);
    __nv_bfloat162 lp0 = __nv_bfloat162(l0, l1), lp1 = __nv_bfloat162(l2, l3);

    uint2 hv, lv;
    hv.x = *(uint32_t*)&hp0; hv.y = *(uint32_t*)&hp1;
    lv.x = *(uint32_t*)&lp0; lv.y = *(uint32_t*)&lp1;
    ((uint2*)(g_hi + (size_t)row * DOUT))[lane] = hv;
    ((uint2*)(g_lo + (size_t)row * DOUT))[lane] = lv;

    if (lane == 0) {
        float n = sqrtf(s);
        g_norm[row]  = n;
        g_rnorm[row] = 1.0f / n;
    }
}

__global__ void reset_kernel() { g_fix_cnt = 0; }

// ---------------------------------------------------------------------------
// Kernel C: mma.sync bf16x3 Gram, 512 threads, 16 warps (4m x 4n),
// warp tile 32x32, K=128 smem-resident, software-pipelined fragments.
// Triangular grid: blockIdx.x in [0,528) -> (bx,by), by >= bx.
// ---------------------------------------------------------------------------
#define OFF_A_HI    0
#define OFF_A_LO    32768
#define OFF_B_HI    65536
#define OFF_B_LO    98304
#define OFF_NA      131072
#define OFF_NB      (OFF_NA + 512)
#define OFF_RNA     (OFF_NB + 512)
#define OFF_RNB     (OFF_RNA + 512)
#define GRAM_SMEM   (OFF_RNB + 512)
#define OFF_STAGE   0
#define STAGE_LD    129

__global__ void __launch_bounds__(512, 1)
gram_mma_kernel(float* __restrict__ out)
{
    // Triangular tile index -> (bx, by) with by >= bx
    int tt = blockIdx.x;
    int by = (int)((sqrtf(8.f * tt + 1.f) - 1.f) * 0.5f);
    while ((by + 1) * (by + 2) / 2 <= tt) by++;
    while (by * (by + 1) / 2 > tt) by--;
    const int bx = tt - by * (by + 1) / 2;
    const int b  = blockIdx.y;

    char* smem = smem_raw;
    const uint32_t sb = smem_u32(smem);
    const int tid  = threadIdx.x;
    const int wid  = tid >> 5;
    const int lane = tid & 31;
    const int warp_m = wid >> 2;          // 0..3
    const int warp_n = wid & 3;           // 0..3

    const int i0 = bx * 128, j0 = by * 128;
    const size_t hbase = (size_t)b * NN * DOUT;
    const size_t nbase = (size_t)b * NN;

    // ---- Load operand tiles (hi/lo for A-rows and B-rows), swizzled ----
    {
        const uint4* srcA_hi = (const uint4*)(g_hi + hbase + (size_t)i0 * DOUT);
        const uint4* srcA_lo = (const uint4*)(g_lo + hbase + (size_t)i0 * DOUT);
        const uint4* srcB_hi = (const uint4*)(g_hi + hbase + (size_t)j0 * DOUT);
        const uint4* srcB_lo = (const uint4*)(g_lo + hbase + (size_t)j0 * DOUT);
#pragma unroll
        for (int t = 0; t < 4; t++) {
            int idx = tid + t * 512;            // 0..2047 uint4 (16B chunks)
            int row = idx >> 4;
            int c   = idx & 15;
            uint32_t off = (uint32_t)(row * 256) + (uint32_t)((c ^ (row & 7)) << 4);
            *(uint4*)(smem + OFF_A_HI + off) = srcA_hi[idx];
            *(uint4*)(smem + OFF_A_LO + off) = srcA_lo[idx];
            *(uint4*)(smem + OFF_B_HI + off) = srcB_hi[idx];
            *(uint4*)(smem + OFF_B_LO + off) = srcB_lo[idx];
        }
        if (tid < 128) {
            ((float*)(smem + OFF_NA))[tid]  = g_norm[nbase + i0 + tid];
            ((float*)(smem + OFF_NB))[tid]  = g_norm[nbase + j0 + tid];
            ((float*)(smem + OFF_RNA))[tid] = g_rnorm[nbase + i0 + tid];
            ((float*)(smem + OFF_RNB))[tid] = g_rnorm[nbase + j0 + tid];
        }
    }
    __syncthreads();

    // ---- MMA mainloop: flattened 24 steps (3 passes x 8 ksteps), pipelined ----
    float acc[2][4][4];
#pragma unroll
    for (int mf = 0; mf < 2; mf++)
#pragma unroll
        for (int nf = 0; nf < 4; nf++)
#pragma unroll
            for (int r = 0; r < 4; r++) acc[mf][nf][r] = 0.f;

    const uint32_t aoffs[3] = { sb + OFF_A_HI, sb + OFF_A_HI, sb + OFF_A_LO };
    const uint32_t boffs[3] = { sb + OFF_B_HI, sb + OFF_B_LO, sb + OFF_B_HI };

    // A fragment: rows warp_m*32 + mf*16 + (lane&15), k-half = lane>>4
    const int a_row  = warp_m * 32 + (lane & 15);
    const int a_ksel = lane >> 4;
    const int a_swz  = a_row & 7;                 // +16 doesn't change low bits
    const uint32_t a_rb0 = (uint32_t)(a_row * 256);
    const uint32_t a_rb1 = (uint32_t)((a_row + 16) * 256);
    // B fragment (non-trans): n-rows warp_n*32 + q*16 + (lane&7)+((lane>>4)<<3)
    const int b_row  = warp_n * 32 + (lane & 7) + ((lane >> 4) << 3);
    const int b_ksel = (lane >> 3) & 1;
    const int b_swz  = b_row & 7;
    const uint32_t b_rb0 = (uint32_t)(b_row * 256);
    const uint32_t b_rb1 = (uint32_t)((b_row + 16) * 256);

    uint32_t abuf[2][2][4], bbuf[2][2][4];

    // prefetch step 0
    {
        uint32_t ac = (uint32_t)((0 * 2 + a_ksel) ^ a_swz) << 4;
        uint32_t bc = (uint32_t)((0 * 2 + b_ksel) ^ b_swz) << 4;
        ldsm_x4(abuf[0][0], aoffs[0] + a_rb0 + ac);
        ldsm_x4(abuf[0][1], aoffs[0] + a_rb1 + ac);
        ldsm_x4(bbuf[0][0], boffs[0] + b_rb0 + bc);
        ldsm_x4(bbuf[0][1], boffs[0] + b_rb1 + bc);
    }

#pragma unroll
    for (int s = 0; s < 24; s++) {
        const int cur = s & 1;
        if (s < 23) {
            const int sn = s + 1;
            const int pn = sn >> 3, kn = sn & 7;
            const int nxt = sn & 1;
            uint32_t ac = (uint32_t)((kn * 2 + a_ksel) ^ a_swz) << 4;
            uint32_t bc = (uint32_t)((kn * 2 + b_ksel) ^ b_swz) << 4;
            ldsm_x4(abuf[nxt][0], aoffs[pn] + a_rb0 + ac);
            ldsm_x4(abuf[nxt][1], aoffs[pn] + a_rb1 + ac);
            ldsm_x4(bbuf[nxt][0], boffs[pn] + b_rb0 + bc);
            ldsm_x4(bbuf[nxt][1], boffs[pn] + b_rb1 + bc);
        }
#pragma unroll
        for (int mf = 0; mf < 2; mf++)
#pragma unroll
            for (int q = 0; q < 2; q++) {
                mma_bf16(acc[mf][q * 2 + 0], abuf[cur][mf], &bbuf[cur][q][0]);
                mma_bf16(acc[mf][q * 2 + 1], abuf[cur][mf], &bbuf[cur][q][2]);
            }
    }
    __syncthreads();   // operand reads done before stage overwrite

    // ---- Epilogue: cosine + abs + threshold + fixup flag, into staging ----
    {
        const float* nA  = (const float*)(smem + OFF_NA);
        const float* nB  = (const float*)(smem + OFF_NB);
        const float* rnA = (const float*)(smem + OFF_RNA);
        const float* rnB = (const float*)(smem + OFF_RNB);
        float* stage = (float*)(smem + OFF_STAGE);

#pragma unroll
        for (int mf = 0; mf < 2; mf++) {
            int r_lo = warp_m * 32 + mf * 16 + (lane >> 2);
#pragma unroll
            for (int half = 0; half < 2; half++) {
                int r = r_lo + half * 8;
                float nm = nA[r], rnm = rnA[r];
#pragma unroll
                for (int nf = 0; nf < 4; nf++) {
                    int c0 = warp_n * 32 + nf * 8 + (lane & 3) * 2;
#pragma unroll
                    for (int e = 0; e < 2; e++) {
                        int c = c0 + e;
                        float dot = acc[mf][nf][half * 2 + e];
                        float t = nm * nB[c];
                        float f = (t >= COS_EPS) ? (rnm * rnB[c]) : (1.0f / COS_EPS);
                        float v = fabsf(dot) * f;
                        if (fabsf(v - THRESHOLD) < FIX_WIN) {
                            unsigned idx = atomicAdd(&g_fix_cnt, 1u);
                            if (idx < MAXFIX)
                                g_fix[idx] = ((unsigned)b << 24) |
                                             ((unsigned)(i0 + r) << 12) |
                                             (unsigned)(j0 + c);
                        }
                        stage[r * STAGE_LD + c] = (v > THRESHOLD) ? v : 0.f;
                    }
                }
            }
        }
    }
    __syncthreads();

    // ---- Coalesced stores: main tile + mirror ----
    {
        const float* stage = (const float*)(smem + OFF_STAGE);
        float* outb = out + (size_t)b * NN * NN;
#pragma unroll
        for (int t = 0; t < 32; t++) {
            int idx = tid + t * 512;
            int r = idx >> 7, c = idx & 127;
            outb[(size_t)(i0 + r) * NN + (j0 + c)] = stage[r * STAGE_LD + c];
        }
        if (bx != by) {
#pragma unroll
            for (int t = 0; t < 32; t++) {
                int idx = tid + t * 512;
                int c = idx >> 7, r = idx & 127;
                outb[(size_t)(j0 + c) * NN + (i0 + r)] = stage[r * STAGE_LD + c];
            }
        }
    }
}

// ---------------------------------------------------------------------------
// Kernel D: exact fp32 fixup of near-threshold entries
// ---------------------------------------------------------------------------
__global__ void __launch_bounds__(256)
fixup_kernel(float* __restrict__ out)
{
    unsigned cnt = g_fix_cnt;
    if (cnt > MAXFIX) cnt = MAXFIX;
    for (unsigned t = blockIdx.x * blockDim.x + threadIdx.x; t < cnt;
         t += gridDim.x * blockDim.x) {
        unsigned e = g_fix[t];
        int b = e >> 24, i = (e >> 12) & 0xFFF, j = e & 0xFFF;
        const float4* hi4 = (const float4*)(g_h + ((size_t)b * NN + i) * DOUT);
        const float4* hj4 = (const float4*)(g_h + ((size_t)b * NN + j) * DOUT);
        float dot = 0.f;
#pragma unroll
        for (int k = 0; k < 32; k++) {
            float4 a = hi4[k], c = hj4[k];
            dot += a.x * c.x + a.y * c.y + a.z * c.z + a.w * c.w;
        }
        float denom = fmaxf(g_norm[(size_t)b * NN + i] * g_norm[(size_t)b * NN + j],
                            COS_EPS);
        float v = fabsf(dot) / denom;
        float r = (v > THRESHOLD) ? v : 0.f;
        float* outb = out + (size_t)b * NN * NN;
        outb[(size_t)i * NN + j] = r;
        outb[(size_t)j * NN + i] = r;
    }
}

// ---------------------------------------------------------------------------
extern "C" void kernel_launch(void* const* d_in, const int* in_sizes, int n_in,
                              void* d_out, int out_size)
{
    (void)in_sizes; (void)n_in; (void)out_size;
    const float* z = (const float*)d_in[0];
    const float* W = (const float*)d_in[1];
    float* out = (float*)d_out;

    const int smem1 = (64 * Z_ROWLEN + 64 * DOUT) * sizeof(float);

    static bool attrs_set = false;
    if (!attrs_set) {
        cudaFuncSetAttribute(gemm1_kernel, cudaFuncAttributeMaxDynamicSharedMemorySize, smem1);
        cudaFuncSetAttribute(gram_mma_kernel, cudaFuncAttributeMaxDynamicSharedMemorySize, GRAM_SMEM);
        attrs_set = true;
    }

    reset_kernel<<<1, 1>>>();
    gemm1_kernel<<<BB * NN / 128, 256, smem1>>>(z, W);
    split_kernel<<<BB * NN / 8, 256>>>();
    dim3 grid(528, BB);
    gram_mma_kernel<<<grid, 512, GRAM_SMEM>>>(out);
    fixup_kernel<<<128, 256>>>(out);
}